// round 8
// baseline (speedup 1.0000x reference)
#include <cuda_runtime.h>
#include <cuda_fp16.h>
#include <cstdint>

// MOELinearB: out[e] = x[e] @ W[e]^T, E=8, N=4096, R=128, OUT=4096, fp32.
// R8: fp16 mma.sync GEMM with FULL-K A fragments held in registers.
//   CTA = 128 rows x 1024-col stripe (8 tiles of 128x128), 1 CTA/SM.
//   A: smem once -> ldmatrix -> ah[8][16] regs (never re-read).
//   B: cp.async double-buffered per tile; only B fragments hit LDSM.

#define E_   8
#define N_   4096
#define R_   128
#define OUT_ 4096

#define BM 128
#define BN 128
#define NTILE 8
#define THREADS 256

#define XTOT (E_ * N_ * R_)
#define WTOT (E_ * OUT_ * R_)

__device__ __half g_xh[XTOT];
__device__ __half g_wh[WTOT];

// Region: 128 rows x 128 fp16, row stride 272 B (256 data + 16 pad).
// (17r + c) mod 8 is a permutation -> ldmatrix and cp.async conflict-free.
#define RSTRIDE_B 272
#define REGION_B  (128 * RSTRIDE_B)         // 34816
#define SMEM_BYTES (3 * REGION_B)           // A + 2 B buffers = 104448

// ---------------- Kernel 1: fp32 -> fp16 ----------------
__global__ __launch_bounds__(256)
void convert_kernel(const float* __restrict__ X, const float* __restrict__ Wt)
{
    const int idx = blockIdx.x * blockDim.x + threadIdx.x;
    const int xq = XTOT / 4;
    const float4* src;
    uint2* dst;
    int base;
    if (idx < xq) {
        src = reinterpret_cast<const float4*>(X);
        dst = reinterpret_cast<uint2*>(g_xh);
        base = idx;
    } else {
        src = reinterpret_cast<const float4*>(Wt);
        dst = reinterpret_cast<uint2*>(g_wh);
        base = idx - xq;
    }
    float4 v = src[base];
    __half2 p0 = __floats2half2_rn(v.x, v.y);
    __half2 p1 = __floats2half2_rn(v.z, v.w);
    dst[base] = make_uint2(*reinterpret_cast<uint32_t*>(&p0),
                           *reinterpret_cast<uint32_t*>(&p1));
}

// ---------------- Kernel 2: GEMM ----------------
static __device__ __forceinline__ void mma_f16(float* d, const uint32_t* a,
                                               const uint32_t* b) {
    asm volatile(
        "mma.sync.aligned.m16n8k16.row.col.f32.f16.f16.f32 "
        "{%0,%1,%2,%3}, {%4,%5,%6,%7}, {%8,%9}, {%0,%1,%2,%3};"
        : "+f"(d[0]), "+f"(d[1]), "+f"(d[2]), "+f"(d[3])
        : "r"(a[0]), "r"(a[1]), "r"(a[2]), "r"(a[3]), "r"(b[0]), "r"(b[1]));
}

static __device__ __forceinline__ void ldsm4(uint32_t* r, uint32_t addr) {
    asm volatile("ldmatrix.sync.aligned.m8n8.x4.shared.b16 {%0,%1,%2,%3}, [%4];"
                 : "=r"(r[0]), "=r"(r[1]), "=r"(r[2]), "=r"(r[3]) : "r"(addr));
}

static __device__ __forceinline__ void cp16(uint32_t dst, const void* src) {
    asm volatile("cp.async.cg.shared.global [%0], [%1], 16;"
                 :: "r"(dst), "l"(src) : "memory");
}

static __device__ __forceinline__ uint32_t smem_u32(const void* p) {
    uint32_t a;
    asm("{ .reg .u64 t; cvta.to.shared.u64 t, %1; cvt.u32.u64 %0, t; }"
        : "=r"(a) : "l"(p));
    return a;
}

__global__ __launch_bounds__(THREADS, 1)
void moe_f16_mma_kernel(float* __restrict__ O)
{
    extern __shared__ char smem[];
    const uint32_t sbase = smem_u32(smem);
    const uint32_t sA  = sbase;
    const uint32_t sB0 = sbase + REGION_B;
    const uint32_t sB1 = sbase + 2 * REGION_B;

    const int tid  = threadIdx.x;
    const int wid  = tid >> 5;
    const int lane = tid & 31;
    const int grp  = lane >> 2;
    const int qc   = lane & 3;
    const int wm   = wid >> 2;   // 0..1
    const int wn   = wid & 3;    // 0..3

    const int e   = blockIdx.z;
    const int bm  = blockIdx.y * BM;
    const int bn0 = blockIdx.x * (BN * NTILE);   // 1024-wide stripe

    const __half* A  = g_xh + (size_t)e * N_   * R_ + (size_t)bm * R_;
    const __half* Bg = g_wh + (size_t)e * OUT_ * R_ + (size_t)bn0 * R_;
    float* C = O + (size_t)e * N_ * OUT_;

    // ldmatrix per-lane offsets
    const uint32_t a_loff = (uint32_t)((wm * 64 + (lane & 15)) * RSTRIDE_B
                                       + (lane >> 4) * 16);
    const uint32_t b_loff = (uint32_t)((wn * 32 + ((lane >> 4) & 1) * 8 + (lane & 7)) * RSTRIDE_B
                                       + ((lane >> 3) & 1) * 16);

    // ---- prologue: stage A (group0) + B0 (group0) + B1 (group1) ----
#pragma unroll
    for (int it = 0; it < 8; it++) {
        const int idx = tid + it * THREADS;
        const int row = idx >> 4;
        const int c   = idx & 15;
        const uint32_t doff = (uint32_t)(row * RSTRIDE_B + c * 16);
        const int goff = row * R_ + c * 8;
        cp16(sA + doff, A + goff);
        cp16(sB0 + doff, Bg + goff);
    }
    asm volatile("cp.async.commit_group;" ::: "memory");
#pragma unroll
    for (int it = 0; it < 8; it++) {
        const int idx = tid + it * THREADS;
        const int row = idx >> 4;
        const int c   = idx & 15;
        cp16(sB1 + (uint32_t)(row * RSTRIDE_B + c * 16),
             Bg + (size_t)BM * R_ + row * R_ + c * 8);
    }
    asm volatile("cp.async.commit_group;" ::: "memory");

    // Wait for A + B0; load ALL A fragments into registers (full K).
    asm volatile("cp.async.wait_group 1;" ::: "memory");
    __syncthreads();

    uint32_t ah[8][16];   // [ks][mt*4 + i] — lives in regs for the whole CTA
#pragma unroll
    for (int ks = 0; ks < 8; ks++)
#pragma unroll
        for (int mt = 0; mt < 4; mt++)
            ldsm4(ah[ks] + mt * 4,
                  sA + a_loff + (uint32_t)(mt * 16 * RSTRIDE_B) + (uint32_t)(ks * 32));

    // ---- tile loop over the 8-tile N-stripe (rolled to keep I$ small) ----
#pragma unroll 1
    for (int t = 0; t < NTILE; t++) {
        if (t > 0) {
            asm volatile("cp.async.wait_group 0;" ::: "memory");
            __syncthreads();   // all warps done reading buf((t+1)&1) in tile t-1
            if (t + 1 < NTILE) {
                const uint32_t sb = (((t + 1) & 1) ? sB1 : sB0);
                const __half* Bt = Bg + (size_t)(t + 1) * BM * R_;
#pragma unroll
                for (int it = 0; it < 8; it++) {
                    const int idx = tid + it * THREADS;
                    const int row = idx >> 4;
                    const int c   = idx & 15;
                    cp16(sb + (uint32_t)(row * RSTRIDE_B + c * 16),
                         Bt + row * R_ + c * 8);
                }
                asm volatile("cp.async.commit_group;" ::: "memory");
            }
        }
        // t == 0: B0 already complete (wait_group 1 above); B1 may still fly.

        const uint32_t bR = ((t & 1) ? sB1 : sB0);

        float acc[4][4][4];
#pragma unroll
        for (int mt = 0; mt < 4; mt++)
#pragma unroll
            for (int nt = 0; nt < 4; nt++)
#pragma unroll
                for (int q = 0; q < 4; q++)
                    acc[mt][nt][q] = 0.0f;

        // B-fragment double buffer across k-steps
        uint32_t bh[2][8];
        ldsm4(bh[0] + 0, bR + b_loff + 0 * 16 * RSTRIDE_B);
        ldsm4(bh[0] + 4, bR + b_loff + 1 * 16 * RSTRIDE_B);

#pragma unroll
        for (int ks = 0; ks < 8; ks++) {
            const int cur = ks & 1;
            if (ks + 1 < 8) {
                const int nxt = cur ^ 1;
                const uint32_t kso = (uint32_t)((ks + 1) * 32);
                ldsm4(bh[nxt] + 0, bR + b_loff + 0 * 16 * RSTRIDE_B + kso);
                ldsm4(bh[nxt] + 4, bR + b_loff + 1 * 16 * RSTRIDE_B + kso);
            }
#pragma unroll
            for (int mt = 0; mt < 4; mt++)
#pragma unroll
                for (int nt = 0; nt < 4; nt++)
                    mma_f16(acc[mt][nt], ah[ks] + mt * 4, bh[cur] + nt * 2);
        }

        // ---- epilogue tile t: streaming stores, drain under tile t+1 ----
        const int colb = bn0 + t * BN;
#pragma unroll
        for (int mt = 0; mt < 4; mt++) {
#pragma unroll
            for (int nt = 0; nt < 4; nt++) {
                const int row = bm + wm * 64 + mt * 16 + grp;
                const int col = colb + wn * 32 + nt * 8 + qc * 2;
                float2 v0 = make_float2(acc[mt][nt][0], acc[mt][nt][1]);
                float2 v1 = make_float2(acc[mt][nt][2], acc[mt][nt][3]);
                __stcs(reinterpret_cast<float2*>(C + (size_t)row * OUT_ + col), v0);
                __stcs(reinterpret_cast<float2*>(C + (size_t)(row + 8) * OUT_ + col), v1);
            }
        }
    }
}

extern "C" void kernel_launch(void* const* d_in, const int* in_sizes, int n_in,
                              void* d_out, int out_size)
{
    const float* x = (const float*)d_in[0];   // [E, N, R]
    const float* w = (const float*)d_in[1];   // [E, OUT, R]
    float* out = (float*)d_out;               // [E, N, OUT]

    const int nvec = (XTOT + WTOT) / 4;
    convert_kernel<<<nvec / 256, 256>>>(x, w);

    cudaFuncSetAttribute(moe_f16_mma_kernel,
                         cudaFuncAttributeMaxDynamicSharedMemorySize, SMEM_BYTES);
    dim3 grid(OUT_ / (BN * NTILE), N_ / BM, E_);   // (4, 32, 8) = 1024 CTAs
    moe_f16_mma_kernel<<<grid, THREADS, SMEM_BYTES>>>(out);
}